// round 1
// baseline (speedup 1.0000x reference)
#include <cuda_runtime.h>
#include <cstdint>
#include <cstddef>

#define Bb   2
#define NH   4
#define Tt   1024
#define Nn   8192
#define Dd   256
#define BHh  (Bb*NH)

// Scratch (device globals; no allocations allowed)
__device__ float g_QR[(size_t)BHh * Tt * Nn];   // 256 MB, RoPE'd Q, tf32-rounded
__device__ float g_gate[BHh * Tt];
__device__ float g_S[(size_t)BHh * Tt * Tt];    // 32 MB fallback scores buffer

// ---------------------------------------------------------------------------
// RoPE + tf32 round: QR[bh,t,n]
// ---------------------------------------------------------------------------
__global__ void rope_kernel(const float* __restrict__ Q) {
    size_t i = (size_t)blockIdx.x * blockDim.x + threadIdx.x;  // pair index
    const size_t npairs = (size_t)BHh * Tt * (Nn / 2);
    if (i >= npairs) return;
    int n2 = (int)(i % (Nn / 2));
    size_t row = i / (Nn / 2);          // bh*T + t
    int t = (int)(row % Tt);
    float nf = (float)(2 * n2);         // q = floor(n/2)*2 == n for even n
    // freq = theta^(-q/N) / (2pi),  theta = 2^16
    float freq = exp2f(-16.0f * nf / (float)Nn) * 0.15915494309189535f;
    float ph = (float)t * freq;
    ph -= floorf(ph);                   // phases % 1.0 (positive)
    float sv, cv;
    __sincosf(ph * 6.283185307179586f, &sv, &cv);
    float2 q = ((const float2*)Q)[i];
    float e = q.x * cv - q.y * sv;      // even lane:  v*c + (-v_odd)*s
    float o = q.y * cv + q.x * sv;      // odd lane:   v*c + ( v_even)*s
    asm("cvt.rna.tf32.f32 %0, %0;" : "+f"(e));
    asm("cvt.rna.tf32.f32 %0, %0;" : "+f"(o));
    ((float2*)g_QR)[i] = make_float2(e, o);
}

// ---------------------------------------------------------------------------
// gate[bh,t] = 0.5 + 0.5*sigmoid(mean_d traces[bh,t,d])
// ---------------------------------------------------------------------------
__global__ void gate_kernel(const float* __restrict__ traces) {
    int warp = (blockIdx.x * blockDim.x + threadIdx.x) >> 5;
    int lane = threadIdx.x & 31;
    if (warp >= BHh * Tt) return;
    const float4* p = (const float4*)(traces + (size_t)warp * Dd);
    float sum = 0.f;
    #pragma unroll
    for (int j = lane; j < Dd / 4; j += 32) {
        float4 v = p[j];
        sum += v.x + v.y + v.z + v.w;
    }
    #pragma unroll
    for (int o = 16; o; o >>= 1) sum += __shfl_xor_sync(0xffffffffu, sum, o);
    if (lane == 0) {
        float m = sum * (1.0f / Dd);
        float g = 1.0f / (1.0f + __expf(-m));
        g_gate[warp] = 0.5f + 0.5f * g;
    }
}

// ---------------------------------------------------------------------------
// tf32 mma helper: m16n8k8, row.col, fp32 accum
// ---------------------------------------------------------------------------
__device__ __forceinline__ void mma8(float c[4], const float a[4], const float b[2]) {
    asm volatile(
        "mma.sync.aligned.m16n8k8.row.col.f32.tf32.tf32.f32 "
        "{%0,%1,%2,%3}, {%4,%5,%6,%7}, {%8,%9}, {%0,%1,%2,%3};\n"
        : "+f"(c[0]), "+f"(c[1]), "+f"(c[2]), "+f"(c[3])
        : "r"(__float_as_uint(a[0])), "r"(__float_as_uint(a[1])),
          "r"(__float_as_uint(a[2])), "r"(__float_as_uint(a[3])),
          "r"(__float_as_uint(b[0])), "r"(__float_as_uint(b[1])));
}

// ---------------------------------------------------------------------------
// scores[bh,t,s] = tril(QR QR^T, -1) * (1 + 0.01 e^{-(t-s)/20} scale) * gate[t]
// 128x128 tiles; grid = 8 bh * 64 (ti,si); si>ti tiles just write zeros.
// ---------------------------------------------------------------------------
__global__ __launch_bounds__(256) void scores_kernel(const float* __restrict__ scale_p,
                                                     float* __restrict__ Sout) {
    const int idx = blockIdx.x;
    const int bh = idx >> 6;
    const int ti = (idx >> 3) & 7;
    const int si = idx & 7;
    float* S = Sout + (size_t)bh * Tt * Tt;
    const int tid = threadIdx.x;

    if (si > ti) {  // strictly-upper block-tile: zero fill
        float4 z = make_float4(0.f, 0.f, 0.f, 0.f);
        #pragma unroll
        for (int p = 0; p < 16; ++p) {
            int e = tid + p * 256;
            int r = e >> 5, c4 = e & 31;
            *(float4*)(S + (size_t)(ti * 128 + r) * Tt + si * 128 + c4 * 4) = z;
        }
        return;
    }

    __shared__ float As[2][128][20];
    __shared__ float Bs[2][128][20];
    const float* Ag = g_QR + (size_t)bh * Tt * Nn + (size_t)(ti * 128) * Nn;
    const float* Bg = g_QR + (size_t)bh * Tt * Nn + (size_t)(si * 128) * Nn;
    const int warp = tid >> 5, lane = tid & 31;
    const int wm = (warp >> 1) * 32, wn = (warp & 1) * 64;
    const int gq = lane >> 2, tg = lane & 3;

    float acc[2][8][4];
    #pragma unroll
    for (int mi = 0; mi < 2; mi++)
        #pragma unroll
        for (int nj = 0; nj < 8; nj++)
            #pragma unroll
            for (int k = 0; k < 4; k++) acc[mi][nj][k] = 0.f;

    const int r0 = tid >> 2;          // 4 float4 per 16-float row
    const int c0 = (tid & 3) * 4;

    float4 ra[2], rb[2];
    #pragma unroll
    for (int p = 0; p < 2; p++) {
        ra[p] = *(const float4*)(Ag + (size_t)(r0 + p * 64) * Nn + c0);
        rb[p] = *(const float4*)(Bg + (size_t)(r0 + p * 64) * Nn + c0);
    }
    #pragma unroll
    for (int p = 0; p < 2; p++) {
        *(float4*)&As[0][r0 + p * 64][c0] = ra[p];
        *(float4*)&Bs[0][r0 + p * 64][c0] = rb[p];
    }
    __syncthreads();

    const int NKT = Nn / 16;  // 512
    for (int kt = 0; kt < NKT; ++kt) {
        int buf = kt & 1;
        if (kt + 1 < NKT) {
            int k0 = (kt + 1) * 16;
            #pragma unroll
            for (int p = 0; p < 2; p++) {
                ra[p] = *(const float4*)(Ag + (size_t)(r0 + p * 64) * Nn + k0 + c0);
                rb[p] = *(const float4*)(Bg + (size_t)(r0 + p * 64) * Nn + k0 + c0);
            }
        }
        #pragma unroll
        for (int ks = 0; ks < 2; ++ks) {
            const int kk = ks * 8;
            float a[2][4], b[8][2];
            #pragma unroll
            for (int mi = 0; mi < 2; mi++) {
                int r = wm + mi * 16;
                a[mi][0] = As[buf][r + gq][kk + tg];
                a[mi][1] = As[buf][r + gq + 8][kk + tg];
                a[mi][2] = As[buf][r + gq][kk + tg + 4];
                a[mi][3] = As[buf][r + gq + 8][kk + tg + 4];
            }
            #pragma unroll
            for (int nj = 0; nj < 8; nj++) {
                int cc = wn + nj * 8 + gq;
                b[nj][0] = Bs[buf][cc][kk + tg];
                b[nj][1] = Bs[buf][cc][kk + tg + 4];
            }
            #pragma unroll
            for (int mi = 0; mi < 2; mi++)
                #pragma unroll
                for (int nj = 0; nj < 8; nj++)
                    mma8(acc[mi][nj], a[mi], b[nj]);
        }
        if (kt + 1 < NKT) {
            int nb = buf ^ 1;
            #pragma unroll
            for (int p = 0; p < 2; p++) {
                *(float4*)&As[nb][r0 + p * 64][c0] = ra[p];
                *(float4*)&Bs[nb][r0 + p * 64][c0] = rb[p];
            }
        }
        __syncthreads();
    }

    const float scale = *scale_p;
    #pragma unroll
    for (int mi = 0; mi < 2; mi++) {
        #pragma unroll
        for (int half = 0; half < 2; ++half) {
            int t = ti * 128 + wm + mi * 16 + gq + half * 8;
            float gt = g_gate[bh * Tt + t];
            #pragma unroll
            for (int nj = 0; nj < 8; nj++) {
                int s0 = si * 128 + wn + nj * 8 + tg * 2;
                float v0 = acc[mi][nj][half * 2 + 0];
                float v1 = acc[mi][nj][half * 2 + 1];
                float o0 = (t > s0)
                    ? v0 * (1.0f + 0.01f * __expf((float)(s0 - t) * 0.05f) * scale) * gt : 0.f;
                float o1 = (t > s0 + 1)
                    ? v1 * (1.0f + 0.01f * __expf((float)(s0 + 1 - t) * 0.05f) * scale) * gt : 0.f;
                *(float2*)(S + (size_t)t * Tt + s0) = make_float2(o0, o1);
            }
        }
    }
}

// ---------------------------------------------------------------------------
// output[bh,t,d] = sum_s scores[bh,t,s] * V[b,s,d]  (only s-blocks <= ti needed)
// ---------------------------------------------------------------------------
__global__ __launch_bounds__(256) void out_kernel(const float* __restrict__ V,
                                                  const float* __restrict__ Sin,
                                                  float* __restrict__ Out) {
    const int idx = blockIdx.x;   // 8 bh * 8 ti * 2 dj
    const int bh = idx >> 4;
    const int ti = (idx >> 1) & 7;
    const int dj = idx & 1;
    const int b = bh >> 2;
    const float* Ag = Sin + (size_t)bh * Tt * Tt + (size_t)(ti * 128) * Tt;
    const float* Bg = V + (size_t)b * Tt * Dd + dj * 128;
    const int tid = threadIdx.x;
    const int warp = tid >> 5, lane = tid & 31;
    const int wm = (warp >> 1) * 32, wn = (warp & 1) * 64;
    const int gq = lane >> 2, tg = lane & 3;

    __shared__ float As[2][128][20];
    __shared__ float Bs[2][16][136];

    float acc[2][8][4];
    #pragma unroll
    for (int mi = 0; mi < 2; mi++)
        #pragma unroll
        for (int nj = 0; nj < 8; nj++)
            #pragma unroll
            for (int k = 0; k < 4; k++) acc[mi][nj][k] = 0.f;

    const int ar = tid >> 2, ac = (tid & 3) * 4;     // A: 128 rows x 16 cols
    const int br = tid >> 5, bc = (tid & 31) * 4;    // B: 16 rows x 128 cols

    float4 ra[2], rb[2];
    #pragma unroll
    for (int p = 0; p < 2; p++) {
        ra[p] = *(const float4*)(Ag + (size_t)(ar + p * 64) * Tt + ac);
        rb[p] = *(const float4*)(Bg + (size_t)(br + p * 8) * Dd + bc);
    }
    #pragma unroll
    for (int p = 0; p < 2; p++) {
        *(float4*)&As[0][ar + p * 64][ac] = ra[p];
        *(float4*)&Bs[0][br + p * 8][bc] = rb[p];
    }
    __syncthreads();

    const int NKT = (ti + 1) * 8;  // s-range [0, (ti+1)*128): rest of S row is 0
    for (int kt = 0; kt < NKT; ++kt) {
        int buf = kt & 1;
        if (kt + 1 < NKT) {
            int k0 = (kt + 1) * 16;
            #pragma unroll
            for (int p = 0; p < 2; p++) {
                ra[p] = *(const float4*)(Ag + (size_t)(ar + p * 64) * Tt + k0 + ac);
                rb[p] = *(const float4*)(Bg + (size_t)(k0 + br + p * 8) * Dd + bc);
            }
        }
        #pragma unroll
        for (int ks = 0; ks < 2; ++ks) {
            const int kk = ks * 8;
            float a[2][4], b[8][2];
            #pragma unroll
            for (int mi = 0; mi < 2; mi++) {
                int r = wm + mi * 16;
                a[mi][0] = As[buf][r + gq][kk + tg];
                a[mi][1] = As[buf][r + gq + 8][kk + tg];
                a[mi][2] = As[buf][r + gq][kk + tg + 4];
                a[mi][3] = As[buf][r + gq + 8][kk + tg + 4];
            }
            #pragma unroll
            for (int nj = 0; nj < 8; nj++) {
                int cc = wn + nj * 8 + gq;
                b[nj][0] = Bs[buf][kk + tg][cc];
                b[nj][1] = Bs[buf][kk + tg + 4][cc];
            }
            // round to tf32 (rna) to avoid truncation bias in HW
            #pragma unroll
            for (int mi = 0; mi < 2; mi++)
                #pragma unroll
                for (int q = 0; q < 4; q++)
                    asm("cvt.rna.tf32.f32 %0, %0;" : "+f"(a[mi][q]));
            #pragma unroll
            for (int nj = 0; nj < 8; nj++) {
                asm("cvt.rna.tf32.f32 %0, %0;" : "+f"(b[nj][0]));
                asm("cvt.rna.tf32.f32 %0, %0;" : "+f"(b[nj][1]));
            }
            #pragma unroll
            for (int mi = 0; mi < 2; mi++)
                #pragma unroll
                for (int nj = 0; nj < 8; nj++)
                    mma8(acc[mi][nj], a[mi], b[nj]);
        }
        if (kt + 1 < NKT) {
            int nb = buf ^ 1;
            #pragma unroll
            for (int p = 0; p < 2; p++) {
                *(float4*)&As[nb][ar + p * 64][ac] = ra[p];
                *(float4*)&Bs[nb][br + p * 8][bc] = rb[p];
            }
        }
        __syncthreads();
    }

    #pragma unroll
    for (int mi = 0; mi < 2; mi++) {
        #pragma unroll
        for (int half = 0; half < 2; ++half) {
            int t = ti * 128 + wm + mi * 16 + gq + half * 8;
            #pragma unroll
            for (int nj = 0; nj < 8; nj++) {
                int n0 = wn + nj * 8 + tg * 2;
                float v0 = acc[mi][nj][half * 2 + 0];
                float v1 = acc[mi][nj][half * 2 + 1];
                *(float2*)(Out + (size_t)bh * Tt * Dd + (size_t)t * Dd + dj * 128 + n0)
                    = make_float2(v0, v1);
            }
        }
    }
}

// ---------------------------------------------------------------------------
extern "C" void kernel_launch(void* const* d_in, const int* in_sizes, int n_in,
                              void* d_out, int out_size) {
    const float* Q      = (const float*)d_in[0];
    const float* V      = (const float*)d_in[1];
    const float* traces = (const float*)d_in[2];
    const float* scale  = (const float*)d_in[3];
    float* out = (float*)d_out;

    // Output layout: output [BH*T*D] then scores [BH*T*T]. Fall back to device
    // scratch for scores if out_size doesn't include them.
    const size_t out_elems    = (size_t)BHh * Tt * Dd;     // 2,097,152
    const size_t scores_elems = (size_t)BHh * Tt * Tt;     // 8,388,608
    float* scores_dst;
    if ((size_t)out_size >= out_elems + scores_elems) {
        scores_dst = out + out_elems;
    } else {
        void* p = nullptr;
        cudaGetSymbolAddress(&p, g_S);
        scores_dst = (float*)p;
    }

    const int npairs = BHh * Tt * (Nn / 2);
    rope_kernel<<<(npairs + 255) / 256, 256>>>(Q);
    gate_kernel<<<(BHh * Tt * 32) / 256, 256>>>(traces);
    scores_kernel<<<BHh * 64, 256>>>(scale, scores_dst);
    out_kernel<<<BHh * 8 * 2, 256>>>(V, scores_dst, out);
}

// round 5
// speedup vs baseline: 1.3975x; 1.3975x over previous
#include <cuda_runtime.h>
#include <cstdint>
#include <cstddef>

#define Bb   2
#define NH   4
#define Tt   1024
#define Nn   8192
#define Dd   256
#define BHh  (Bb*NH)

// Scratch (device globals; no allocations allowed)
__device__ float g_QR[(size_t)BHh * Tt * Nn];   // 256 MB, RoPE'd Q, tf32-rounded
__device__ float g_gate[BHh * Tt];
__device__ float g_S[(size_t)BHh * Tt * Tt];    // 32 MB fallback scores buffer

__device__ __forceinline__ void cpasync16(uint32_t s, const void* g) {
    asm volatile("cp.async.cg.shared.global [%0], [%1], 16;" :: "r"(s), "l"(g));
}
__device__ __forceinline__ uint32_t smem_u32(const void* p) {
    uint32_t a;
    asm("{ .reg .u64 t; cvta.to.shared.u64 t, %1; cvt.u32.u64 %0, t; }"
        : "=r"(a) : "l"(p));
    return a;
}

// ---------------------------------------------------------------------------
// RoPE + tf32 round: QR[bh,t,n]
// ---------------------------------------------------------------------------
__global__ void rope_kernel(const float* __restrict__ Q) {
    size_t i = (size_t)blockIdx.x * blockDim.x + threadIdx.x;  // pair index
    const size_t npairs = (size_t)BHh * Tt * (Nn / 2);
    if (i >= npairs) return;
    int n2 = (int)(i % (Nn / 2));
    size_t row = i / (Nn / 2);
    int t = (int)(row % Tt);
    float nf = (float)(2 * n2);
    float freq = exp2f(-16.0f * nf / (float)Nn) * 0.15915494309189535f;
    float ph = (float)t * freq;
    ph -= floorf(ph);
    float sv, cv;
    __sincosf(ph * 6.283185307179586f, &sv, &cv);
    float2 q = ((const float2*)Q)[i];
    float e = q.x * cv - q.y * sv;
    float o = q.y * cv + q.x * sv;
    asm("cvt.rna.tf32.f32 %0, %0;" : "+f"(e));
    asm("cvt.rna.tf32.f32 %0, %0;" : "+f"(o));
    ((float2*)g_QR)[i] = make_float2(e, o);
}

// ---------------------------------------------------------------------------
// gate[bh,t] = 0.5 + 0.5*sigmoid(mean_d traces[bh,t,d])
// ---------------------------------------------------------------------------
__global__ void gate_kernel(const float* __restrict__ traces) {
    int warp = (blockIdx.x * blockDim.x + threadIdx.x) >> 5;
    int lane = threadIdx.x & 31;
    if (warp >= BHh * Tt) return;
    const float4* p = (const float4*)(traces + (size_t)warp * Dd);
    float sum = 0.f;
    #pragma unroll
    for (int j = lane; j < Dd / 4; j += 32) {
        float4 v = p[j];
        sum += v.x + v.y + v.z + v.w;
    }
    #pragma unroll
    for (int o = 16; o; o >>= 1) sum += __shfl_xor_sync(0xffffffffu, sum, o);
    if (lane == 0) {
        float m = sum * (1.0f / Dd);
        float g = 1.0f / (1.0f + __expf(-m));
        g_gate[warp] = 0.5f + 0.5f * g;
    }
}

// ---------------------------------------------------------------------------
// tf32 mma helper: m16n8k8, row.col, fp32 accum
// ---------------------------------------------------------------------------
__device__ __forceinline__ void mma8(float c[4], const float a[4], const float b[2]) {
    asm volatile(
        "mma.sync.aligned.m16n8k8.row.col.f32.tf32.tf32.f32 "
        "{%0,%1,%2,%3}, {%4,%5,%6,%7}, {%8,%9}, {%0,%1,%2,%3};\n"
        : "+f"(c[0]), "+f"(c[1]), "+f"(c[2]), "+f"(c[3])
        : "r"(__float_as_uint(a[0])), "r"(__float_as_uint(a[1])),
          "r"(__float_as_uint(a[2])), "r"(__float_as_uint(a[3])),
          "r"(__float_as_uint(b[0])), "r"(__float_as_uint(b[1])));
}

// ---------------------------------------------------------------------------
// scores[bh,t,s]: 128x128 tile per CTA, 128 threads (4 warps @ 64x64),
// cp.async 4-stage ring (K=32 chunks), SW128-swizzled smem, 1 bar/chunk.
// grid: bh*64 + ti*8 + si ; si>ti tiles zero-filled.
// ---------------------------------------------------------------------------
#define KC      32
#define NCHUNK  (Nn / KC)                // 256
#define STAGES  4
#define STAGE_B (256 * 128)              // (128 A rows + 128 B rows) * 128B
#define SCORES_SMEM (STAGES * STAGE_B)   // 131072

__global__ __launch_bounds__(128, 1) void scores_mma(const float* __restrict__ scale_p,
                                                     float* __restrict__ Sout) {
    const int idx = blockIdx.x;
    const int bh = idx >> 6;
    const int ti = (idx >> 3) & 7;
    const int si = idx & 7;
    float* S = Sout + (size_t)bh * Tt * Tt;
    const int tid = threadIdx.x;

    if (si > ti) {  // strictly-upper block-tile: zero fill (d_out is poisoned)
        float4 z = make_float4(0.f, 0.f, 0.f, 0.f);
        #pragma unroll
        for (int p = 0; p < 32; ++p) {
            int e = tid + p * 128;
            int r = e >> 5, c = (e & 31) * 4;
            *(float4*)(S + (size_t)(ti * 128 + r) * Tt + si * 128 + c) = z;
        }
        return;
    }

    extern __shared__ char smem[];
    const uint32_t sbase = smem_u32(smem);

    const float* Ag = g_QR + (size_t)bh * Tt * Nn + (size_t)(ti * 128) * Nn;
    const float* Bg = g_QR + (size_t)bh * Tt * Nn + (size_t)(si * 128) * Nn;

    const int warp = tid >> 5, lane = tid & 31;
    const int wm = (warp >> 1) * 64, wn = (warp & 1) * 64;
    const int gq = lane >> 2, tg = lane & 3;

    // cp.async mapping: 128 threads cover 256 rows x 8 cols of 16B
    const int col = tid & 7;          // 16B column
    const int r0  = tid >> 3;         // 0..15

    auto load_stage = [&](int stage, int chunk) {
        const int k0 = chunk * KC;
        const uint32_t base = sbase + stage * STAGE_B;
        const float* gA = Ag + k0 + col * 4;
        #pragma unroll
        for (int i = 0; i < 8; i++) {
            int r = r0 + i * 16;
            cpasync16(base + r * 128 + ((col ^ (r & 7)) << 4),
                      gA + (size_t)r * Nn);
        }
        const uint32_t bb = base + 128 * 128;
        const float* gB = Bg + k0 + col * 4;
        #pragma unroll
        for (int i = 0; i < 8; i++) {
            int r = r0 + i * 16;
            cpasync16(bb + r * 128 + ((col ^ (r & 7)) << 4),
                      gB + (size_t)r * Nn);
        }
        asm volatile("cp.async.commit_group;" ::: "memory");
    };

    #pragma unroll
    for (int s = 0; s < 3; s++) load_stage(s, s);

    float acc[4][8][4];
    #pragma unroll
    for (int mi = 0; mi < 4; mi++)
        #pragma unroll
        for (int nj = 0; nj < 8; nj++)
            #pragma unroll
            for (int k = 0; k < 4; k++) acc[mi][nj][k] = 0.f;

    for (int c = 0; c < NCHUNK; c++) {
        asm volatile("cp.async.wait_group 2;" ::: "memory");
        __syncthreads();
        if (c + 3 < NCHUNK) load_stage((c + 3) & 3, c + 3);
        else asm volatile("cp.async.commit_group;" ::: "memory");

        const uint32_t abase = sbase + (c & 3) * STAGE_B;
        const uint32_t bbase = abase + 128 * 128;

        #pragma unroll
        for (int ks = 0; ks < 4; ks++) {
            const int kk = ks * 8;
            const uint32_t ca = (uint32_t)(((kk + tg) * 4) ^ (gq << 4));
            float a[4][4], b[8][2];
            #pragma unroll
            for (int mi = 0; mi < 4; mi++) {
                uint32_t p = abase + (uint32_t)((wm + mi * 16 + gq) * 128) + ca;
                asm("ld.shared.f32 %0, [%1];" : "=f"(a[mi][0]) : "r"(p));
                asm("ld.shared.f32 %0, [%1];" : "=f"(a[mi][1]) : "r"(p + 1024));
                asm("ld.shared.f32 %0, [%1];" : "=f"(a[mi][2]) : "r"(p ^ 16));
                asm("ld.shared.f32 %0, [%1];" : "=f"(a[mi][3]) : "r"((p + 1024) ^ 16));
            }
            #pragma unroll
            for (int nj = 0; nj < 8; nj++) {
                uint32_t p = bbase + (uint32_t)((wn + nj * 8 + gq) * 128) + ca;
                asm("ld.shared.f32 %0, [%1];" : "=f"(b[nj][0]) : "r"(p));
                asm("ld.shared.f32 %0, [%1];" : "=f"(b[nj][1]) : "r"(p ^ 16));
            }
            #pragma unroll
            for (int mi = 0; mi < 4; mi++)
                #pragma unroll
                for (int nj = 0; nj < 8; nj++)
                    mma8(acc[mi][nj], a[mi], b[nj]);
        }
    }

    // epilogue: STDP * strict-lower mask * gate
    const float scale = *scale_p;
    #pragma unroll
    for (int mi = 0; mi < 4; mi++) {
        #pragma unroll
        for (int half = 0; half < 2; ++half) {
            int t = ti * 128 + wm + mi * 16 + gq + half * 8;
            float gt = g_gate[bh * Tt + t];
            #pragma unroll
            for (int nj = 0; nj < 8; nj++) {
                int s0 = si * 128 + wn + nj * 8 + tg * 2;
                float v0 = acc[mi][nj][half * 2 + 0];
                float v1 = acc[mi][nj][half * 2 + 1];
                float o0 = (t > s0)
                    ? v0 * (1.0f + 0.01f * __expf((float)(s0 - t) * 0.05f) * scale) * gt : 0.f;
                float o1 = (t > s0 + 1)
                    ? v1 * (1.0f + 0.01f * __expf((float)(s0 + 1 - t) * 0.05f) * scale) * gt : 0.f;
                *(float2*)(S + (size_t)t * Tt + s0) = make_float2(o0, o1);
            }
        }
    }
}

// ---------------------------------------------------------------------------
// output[bh,t,d] = sum_s scores[bh,t,s] * V[b,s,d]  (only s-blocks <= ti needed)
// ---------------------------------------------------------------------------
__global__ __launch_bounds__(256) void out_kernel(const float* __restrict__ V,
                                                  const float* __restrict__ Sin,
                                                  float* __restrict__ Out) {
    const int idx = blockIdx.x;   // 8 bh * 8 ti * 2 dj
    const int bh = idx >> 4;
    const int ti = (idx >> 1) & 7;
    const int dj = idx & 1;
    const int b = bh >> 2;
    const float* Ag = Sin + (size_t)bh * Tt * Tt + (size_t)(ti * 128) * Tt;
    const float* Bg = V + (size_t)b * Tt * Dd + dj * 128;
    const int tid = threadIdx.x;
    const int warp = tid >> 5, lane = tid & 31;
    const int wm = (warp >> 1) * 32, wn = (warp & 1) * 64;
    const int gq = lane >> 2, tg = lane & 3;

    __shared__ float As[2][128][20];
    __shared__ float Bs[2][16][136];

    float acc[2][8][4];
    #pragma unroll
    for (int mi = 0; mi < 2; mi++)
        #pragma unroll
        for (int nj = 0; nj < 8; nj++)
            #pragma unroll
            for (int k = 0; k < 4; k++) acc[mi][nj][k] = 0.f;

    const int ar = tid >> 2, ac = (tid & 3) * 4;
    const int br = tid >> 5, bc = (tid & 31) * 4;

    float4 ra[2], rb[2];
    #pragma unroll
    for (int p = 0; p < 2; p++) {
        ra[p] = *(const float4*)(Ag + (size_t)(ar + p * 64) * Tt + ac);
        rb[p] = *(const float4*)(Bg + (size_t)(br + p * 8) * Dd + bc);
    }
    #pragma unroll
    for (int p = 0; p < 2; p++) {
        *(float4*)&As[0][ar + p * 64][ac] = ra[p];
        *(float4*)&Bs[0][br + p * 8][bc] = rb[p];
    }
    __syncthreads();

    const int NKT = (ti + 1) * 8;
    for (int kt = 0; kt < NKT; ++kt) {
        int buf = kt & 1;
        if (kt + 1 < NKT) {
            int k0 = (kt + 1) * 16;
            #pragma unroll
            for (int p = 0; p < 2; p++) {
                ra[p] = *(const float4*)(Ag + (size_t)(ar + p * 64) * Tt + k0 + ac);
                rb[p] = *(const float4*)(Bg + (size_t)(k0 + br + p * 8) * Dd + bc);
            }
        }
        #pragma unroll
        for (int ks = 0; ks < 2; ++ks) {
            const int kk = ks * 8;
            float a[2][4], b2[8][2];
            #pragma unroll
            for (int mi = 0; mi < 2; mi++) {
                int r = wm + mi * 16;
                a[mi][0] = As[buf][r + gq][kk + tg];
                a[mi][1] = As[buf][r + gq + 8][kk + tg];
                a[mi][2] = As[buf][r + gq][kk + tg + 4];
                a[mi][3] = As[buf][r + gq + 8][kk + tg + 4];
            }
            #pragma unroll
            for (int nj = 0; nj < 8; nj++) {
                int cc = wn + nj * 8 + gq;
                b2[nj][0] = Bs[buf][kk + tg][cc];
                b2[nj][1] = Bs[buf][kk + tg + 4][cc];
            }
            #pragma unroll
            for (int mi = 0; mi < 2; mi++)
                #pragma unroll
                for (int q = 0; q < 4; q++)
                    asm("cvt.rna.tf32.f32 %0, %0;" : "+f"(a[mi][q]));
            #pragma unroll
            for (int nj = 0; nj < 8; nj++) {
                asm("cvt.rna.tf32.f32 %0, %0;" : "+f"(b2[nj][0]));
                asm("cvt.rna.tf32.f32 %0, %0;" : "+f"(b2[nj][1]));
            }
            #pragma unroll
            for (int mi = 0; mi < 2; mi++)
                #pragma unroll
                for (int nj = 0; nj < 8; nj++)
                    mma8(acc[mi][nj], a[mi], b2[nj]);
        }
        if (kt + 1 < NKT) {
            int nb = buf ^ 1;
            #pragma unroll
            for (int p = 0; p < 2; p++) {
                *(float4*)&As[nb][ar + p * 64][ac] = ra[p];
                *(float4*)&Bs[nb][br + p * 8][bc] = rb[p];
            }
        }
        __syncthreads();
    }

    #pragma unroll
    for (int mi = 0; mi < 2; mi++) {
        #pragma unroll
        for (int half = 0; half < 2; ++half) {
            int t = ti * 128 + wm + mi * 16 + gq + half * 8;
            #pragma unroll
            for (int nj = 0; nj < 8; nj++) {
                int n0 = wn + nj * 8 + tg * 2;
                float v0 = acc[mi][nj][half * 2 + 0];
                float v1 = acc[mi][nj][half * 2 + 1];
                *(float2*)(Out + (size_t)bh * Tt * Dd + (size_t)t * Dd + dj * 128 + n0)
                    = make_float2(v0, v1);
            }
        }
    }
}

// ---------------------------------------------------------------------------
extern "C" void kernel_launch(void* const* d_in, const int* in_sizes, int n_in,
                              void* d_out, int out_size) {
    const float* Q      = (const float*)d_in[0];
    const float* V      = (const float*)d_in[1];
    const float* traces = (const float*)d_in[2];
    const float* scale  = (const float*)d_in[3];
    float* out = (float*)d_out;

    const size_t out_elems    = (size_t)BHh * Tt * Dd;
    const size_t scores_elems = (size_t)BHh * Tt * Tt;
    float* scores_dst;
    if ((size_t)out_size >= out_elems + scores_elems) {
        scores_dst = out + out_elems;
    } else {
        void* p = nullptr;
        cudaGetSymbolAddress(&p, g_S);
        scores_dst = (float*)p;
    }

    cudaFuncSetAttribute(scores_mma, cudaFuncAttributeMaxDynamicSharedMemorySize,
                         SCORES_SMEM);

    const int npairs = BHh * Tt * (Nn / 2);
    rope_kernel<<<(npairs + 255) / 256, 256>>>(Q);
    gate_kernel<<<(BHh * Tt * 32) / 256, 256>>>(traces);
    scores_mma<<<BHh * 64, 128, SCORES_SMEM>>>(scale, scores_dst);
    out_kernel<<<BHh * 8 * 2, 256>>>(V, scores_dst, out);
}

// round 7
// speedup vs baseline: 1.4173x; 1.0141x over previous
#include <cuda_runtime.h>
#include <cstdint>
#include <cstddef>

#define Bb   2
#define NH   4
#define Tt   1024
#define Nn   8192
#define Dd   256
#define BHh  (Bb*NH)

// Scratch (device globals; no allocations allowed)
__device__ float g_QR[(size_t)BHh * Tt * Nn];   // 256 MB, RoPE'd Q, tf32-rounded
__device__ float g_gate[BHh * Tt];
__device__ float g_S[(size_t)BHh * Tt * Tt];    // 32 MB fallback scores buffer

__device__ __forceinline__ void cpasync16(uint32_t s, const void* g) {
    asm volatile("cp.async.cg.shared.global [%0], [%1], 16;" :: "r"(s), "l"(g));
}
__device__ __forceinline__ uint32_t smem_u32(const void* p) {
    uint32_t a;
    asm("{ .reg .u64 t; cvta.to.shared.u64 t, %1; cvt.u32.u64 %0, t; }"
        : "=r"(a) : "l"(p));
    return a;
}

// ---------------------------------------------------------------------------
// RoPE + tf32 round: QR[bh,t,n]
// ---------------------------------------------------------------------------
__global__ void rope_kernel(const float* __restrict__ Q) {
    size_t i = (size_t)blockIdx.x * blockDim.x + threadIdx.x;  // pair index
    const size_t npairs = (size_t)BHh * Tt * (Nn / 2);
    if (i >= npairs) return;
    int n2 = (int)(i % (Nn / 2));
    size_t row = i / (Nn / 2);
    int t = (int)(row % Tt);
    float nf = (float)(2 * n2);
    float freq = exp2f(-16.0f * nf / (float)Nn) * 0.15915494309189535f;
    float ph = (float)t * freq;
    ph -= floorf(ph);
    float sv, cv;
    __sincosf(ph * 6.283185307179586f, &sv, &cv);
    float2 q = ((const float2*)Q)[i];
    float e = q.x * cv - q.y * sv;
    float o = q.y * cv + q.x * sv;
    asm("cvt.rna.tf32.f32 %0, %0;" : "+f"(e));
    asm("cvt.rna.tf32.f32 %0, %0;" : "+f"(o));
    ((float2*)g_QR)[i] = make_float2(e, o);
}

// ---------------------------------------------------------------------------
// gate[bh,t] = 0.5 + 0.5*sigmoid(mean_d traces[bh,t,d])
// ---------------------------------------------------------------------------
__global__ void gate_kernel(const float* __restrict__ traces) {
    int warp = (blockIdx.x * blockDim.x + threadIdx.x) >> 5;
    int lane = threadIdx.x & 31;
    if (warp >= BHh * Tt) return;
    const float4* p = (const float4*)(traces + (size_t)warp * Dd);
    float sum = 0.f;
    #pragma unroll
    for (int j = lane; j < Dd / 4; j += 32) {
        float4 v = p[j];
        sum += v.x + v.y + v.z + v.w;
    }
    #pragma unroll
    for (int o = 16; o; o >>= 1) sum += __shfl_xor_sync(0xffffffffu, sum, o);
    if (lane == 0) {
        float m = sum * (1.0f / Dd);
        float g = 1.0f / (1.0f + __expf(-m));
        g_gate[warp] = 0.5f + 0.5f * g;
    }
}

// ---------------------------------------------------------------------------
// tf32 mma helper: m16n8k8, row.col, fp32 accum
// ---------------------------------------------------------------------------
__device__ __forceinline__ void mma8(float c[4], const float a[4], const float b[2]) {
    asm volatile(
        "mma.sync.aligned.m16n8k8.row.col.f32.tf32.tf32.f32 "
        "{%0,%1,%2,%3}, {%4,%5,%6,%7}, {%8,%9}, {%0,%1,%2,%3};\n"
        : "+f"(c[0]), "+f"(c[1]), "+f"(c[2]), "+f"(c[3])
        : "r"(__float_as_uint(a[0])), "r"(__float_as_uint(a[1])),
          "r"(__float_as_uint(a[2])), "r"(__float_as_uint(a[3])),
          "r"(__float_as_uint(b[0])), "r"(__float_as_uint(b[1])));
}

// ---------------------------------------------------------------------------
// scores[bh,t,s]: 128x128 tile per CTA, 256 threads (8 warps @ 32x64),
// cp.async 4-stage ring (K=32 chunks), swizzled smem, 1 bar/chunk.
// grid: bh*64 + ti*8 + si ; si>ti tiles zero-filled.
// ---------------------------------------------------------------------------
#define KC      32
#define NCHUNK  (Nn / KC)                // 256
#define STAGE_B (256 * 128)              // (128 A rows + 128 B rows) * 128B
#define SCORES_SMEM (4 * STAGE_B)        // 131072

__global__ __launch_bounds__(256, 1) void scores_mma(const float* __restrict__ scale_p,
                                                     float* __restrict__ Sout) {
    const int idx = blockIdx.x;
    const int bh = idx >> 6;
    const int ti = (idx >> 3) & 7;
    const int si = idx & 7;
    float* S = Sout + (size_t)bh * Tt * Tt;
    const int tid = threadIdx.x;

    if (si > ti) {  // strictly-upper block-tile: zero fill (d_out is poisoned)
        float4 z = make_float4(0.f, 0.f, 0.f, 0.f);
        #pragma unroll
        for (int p = 0; p < 16; ++p) {
            int e = tid + p * 256;
            int r = e >> 5, c = (e & 31) * 4;
            *(float4*)(S + (size_t)(ti * 128 + r) * Tt + si * 128 + c) = z;
        }
        return;
    }

    extern __shared__ char smem[];
    const uint32_t sbase = smem_u32(smem);

    const float* Ag = g_QR + (size_t)bh * Tt * Nn + (size_t)(ti * 128) * Nn;
    const float* Bg = g_QR + (size_t)bh * Tt * Nn + (size_t)(si * 128) * Nn;

    const int warp = tid >> 5, lane = tid & 31;
    const int wm = (warp >> 1) * 32, wn = (warp & 1) * 64;
    const int gq = lane >> 2, tg = lane & 3;

    // cp.async mapping: 256 threads cover 256 rows x 8 cols of 16B
    const int col = tid & 7;          // 16B column
    const int r0  = tid >> 3;         // 0..31

    auto load_stage = [&](int stage, int chunk) {
        const int k0 = chunk * KC;
        const uint32_t base = sbase + stage * STAGE_B;
        const float* gA = Ag + k0 + col * 4;
        #pragma unroll
        for (int i = 0; i < 4; i++) {
            int r = r0 + i * 32;
            cpasync16(base + r * 128 + ((col ^ (r & 7)) << 4),
                      gA + (size_t)r * Nn);
        }
        const uint32_t bb = base + 128 * 128;
        const float* gB = Bg + k0 + col * 4;
        #pragma unroll
        for (int i = 0; i < 4; i++) {
            int r = r0 + i * 32;
            cpasync16(bb + r * 128 + ((col ^ (r & 7)) << 4),
                      gB + (size_t)r * Nn);
        }
        asm volatile("cp.async.commit_group;" ::: "memory");
    };

    #pragma unroll
    for (int s = 0; s < 3; s++) load_stage(s, s);

    float acc[2][8][4];
    #pragma unroll
    for (int mi = 0; mi < 2; mi++)
        #pragma unroll
        for (int nj = 0; nj < 8; nj++)
            #pragma unroll
            for (int k = 0; k < 4; k++) acc[mi][nj][k] = 0.f;

    for (int c = 0; c < NCHUNK; c++) {
        asm volatile("cp.async.wait_group 2;" ::: "memory");
        __syncthreads();
        if (c + 3 < NCHUNK) load_stage((c + 3) & 3, c + 3);
        else asm volatile("cp.async.commit_group;" ::: "memory");

        const uint32_t abase = sbase + (c & 3) * STAGE_B;
        const uint32_t bbase = abase + 128 * 128;

        #pragma unroll
        for (int ks = 0; ks < 4; ks++) {
            const int kk = ks * 8;
            const uint32_t ca = (uint32_t)(((kk + tg) * 4) ^ (gq << 4));
            float a[2][4], b[8][2];
            #pragma unroll
            for (int mi = 0; mi < 2; mi++) {
                uint32_t p = abase + (uint32_t)((wm + mi * 16 + gq) * 128) + ca;
                asm("ld.shared.f32 %0, [%1];" : "=f"(a[mi][0]) : "r"(p));
                asm("ld.shared.f32 %0, [%1];" : "=f"(a[mi][1]) : "r"(p + 1024));
                asm("ld.shared.f32 %0, [%1];" : "=f"(a[mi][2]) : "r"(p ^ 16));
                asm("ld.shared.f32 %0, [%1];" : "=f"(a[mi][3]) : "r"((p + 1024) ^ 16));
            }
            #pragma unroll
            for (int nj = 0; nj < 8; nj++) {
                uint32_t p = bbase + (uint32_t)((wn + nj * 8 + gq) * 128) + ca;
                asm("ld.shared.f32 %0, [%1];" : "=f"(b[nj][0]) : "r"(p));
                asm("ld.shared.f32 %0, [%1];" : "=f"(b[nj][1]) : "r"(p ^ 16));
            }
            #pragma unroll
            for (int mi = 0; mi < 2; mi++)
                #pragma unroll
                for (int nj = 0; nj < 8; nj++)
                    mma8(acc[mi][nj], a[mi], b[nj]);
        }
    }

    // epilogue: STDP * strict-lower mask * gate
    const float scale = *scale_p;
    #pragma unroll
    for (int mi = 0; mi < 2; mi++) {
        #pragma unroll
        for (int half = 0; half < 2; ++half) {
            int t = ti * 128 + wm + mi * 16 + gq + half * 8;
            float gt = g_gate[bh * Tt + t];
            #pragma unroll
            for (int nj = 0; nj < 8; nj++) {
                int s0 = si * 128 + wn + nj * 8 + tg * 2;
                float v0 = acc[mi][nj][half * 2 + 0];
                float v1 = acc[mi][nj][half * 2 + 1];
                float o0 = (t > s0)
                    ? v0 * (1.0f + 0.01f * __expf((float)(s0 - t) * 0.05f) * scale) * gt : 0.f;
                float o1 = (t > s0 + 1)
                    ? v1 * (1.0f + 0.01f * __expf((float)(s0 + 1 - t) * 0.05f) * scale) * gt : 0.f;
                *(float2*)(S + (size_t)t * Tt + s0) = make_float2(o0, o1);
            }
        }
    }
}

// ---------------------------------------------------------------------------
// out[bh,t,d] = sum_s S[bh,t,s] * V[b,s,d], pipelined like scores_mma.
// CTA: 128 t-rows x 128 d-cols (dj half), K=(ti+1)*128, 256 threads.
// A stage: 128x128B (S rows, swizzled). B stage: 32 rows x 544B (V, padded).
// ---------------------------------------------------------------------------
#define OSTAGE_A (128 * 128)             // 16384
#define OSTAGE_B (32 * 544)              // 17408
#define OSTAGE   (OSTAGE_A + OSTAGE_B)   // 33792
#define OUT_SMEM (4 * OSTAGE)            // 135168

__global__ __launch_bounds__(256, 1) void out_mma(const float* __restrict__ V,
                                                  const float* __restrict__ Sin,
                                                  float* __restrict__ Out) {
    const int idx = blockIdx.x;   // 8 bh * 8 ti * 2 dj
    const int bh = idx >> 4;
    const int ti = (idx >> 1) & 7;
    const int dj = idx & 1;
    const int b = bh >> 2;
    const float* Ag = Sin + (size_t)bh * Tt * Tt + (size_t)(ti * 128) * Tt;
    const float* Bg = V + (size_t)b * Tt * Dd + dj * 128;
    const int tid = threadIdx.x;

    extern __shared__ char smem[];
    const uint32_t sbase = smem_u32(smem);

    const int warp = tid >> 5, lane = tid & 31;
    const int wm = (warp >> 1) * 32, wn = (warp & 1) * 64;
    const int gq = lane >> 2, tg = lane & 3;

    const int col = tid & 7, r0 = tid >> 3;      // A loader
    const int brl = tid >> 5, bc16 = tid & 31;   // B loader

    auto load_stage = [&](int stage, int chunk) {
        const int k0 = chunk * KC;
        const uint32_t base = sbase + stage * OSTAGE;
        const float* gA = Ag + k0 + col * 4;
        #pragma unroll
        for (int i = 0; i < 4; i++) {
            int r = r0 + i * 32;
            cpasync16(base + r * 128 + ((col ^ (r & 7)) << 4),
                      gA + (size_t)r * Tt);
        }
        const uint32_t bb = base + OSTAGE_A;
        #pragma unroll
        for (int i = 0; i < 4; i++) {
            int r = brl + i * 8;                 // V row s = k0 + r
            cpasync16(bb + r * 544 + bc16 * 16,
                      Bg + (size_t)(k0 + r) * Dd + bc16 * 4);
        }
        asm volatile("cp.async.commit_group;" ::: "memory");
    };

    const int NKT = (ti + 1) * 4;   // K chunks of 32
    #pragma unroll
    for (int s = 0; s < 3; s++) load_stage(s, s);

    float acc[2][8][4];
    #pragma unroll
    for (int mi = 0; mi < 2; mi++)
        #pragma unroll
        for (int nj = 0; nj < 8; nj++)
            #pragma unroll
            for (int k = 0; k < 4; k++) acc[mi][nj][k] = 0.f;

    for (int c = 0; c < NKT; c++) {
        asm volatile("cp.async.wait_group 2;" ::: "memory");
        __syncthreads();
        if (c + 3 < NKT) load_stage((c + 3) & 3, c + 3);
        else asm volatile("cp.async.commit_group;" ::: "memory");

        const uint32_t abase = sbase + (c & 3) * OSTAGE;
        const uint32_t bbase = abase + OSTAGE_A;

        #pragma unroll
        for (int ks = 0; ks < 4; ks++) {
            const int kk = ks * 8;
            const uint32_t ca = (uint32_t)(((kk + tg) * 4) ^ (gq << 4));
            float a[2][4], bfr[8][2];
            #pragma unroll
            for (int mi = 0; mi < 2; mi++) {
                uint32_t p = abase + (uint32_t)((wm + mi * 16 + gq) * 128) + ca;
                asm("ld.shared.f32 %0, [%1];" : "=f"(a[mi][0]) : "r"(p));
                asm("ld.shared.f32 %0, [%1];" : "=f"(a[mi][1]) : "r"(p + 1024));
                asm("ld.shared.f32 %0, [%1];" : "=f"(a[mi][2]) : "r"(p ^ 16));
                asm("ld.shared.f32 %0, [%1];" : "=f"(a[mi][3]) : "r"((p + 1024) ^ 16));
            }
            #pragma unroll
            for (int nj = 0; nj < 8; nj++) {
                uint32_t c16f = (uint32_t)(((wn + nj * 8) >> 2) + (gq >> 2));
                uint32_t p = bbase + (uint32_t)((kk + tg) * 544)
                           + (c16f << 4) + (uint32_t)((gq & 3) * 4);
                asm("ld.shared.f32 %0, [%1];" : "=f"(bfr[nj][0]) : "r"(p));
                asm("ld.shared.f32 %0, [%1];" : "=f"(bfr[nj][1]) : "r"(p + 4 * 544));
            }
            #pragma unroll
            for (int mi = 0; mi < 2; mi++)
                #pragma unroll
                for (int q = 0; q < 4; q++)
                    asm("cvt.rna.tf32.f32 %0, %0;" : "+f"(a[mi][q]));
            #pragma unroll
            for (int nj = 0; nj < 8; nj++) {
                asm("cvt.rna.tf32.f32 %0, %0;" : "+f"(bfr[nj][0]));
                asm("cvt.rna.tf32.f32 %0, %0;" : "+f"(bfr[nj][1]));
            }
            #pragma unroll
            for (int mi = 0; mi < 2; mi++)
                #pragma unroll
                for (int nj = 0; nj < 8; nj++)
                    mma8(acc[mi][nj], a[mi], bfr[nj]);
        }
    }

    #pragma unroll
    for (int mi = 0; mi < 2; mi++) {
        #pragma unroll
        for (int half = 0; half < 2; ++half) {
            int t = ti * 128 + wm + mi * 16 + gq + half * 8;
            #pragma unroll
            for (int nj = 0; nj < 8; nj++) {
                int n0 = wn + nj * 8 + tg * 2;
                float v0 = acc[mi][nj][half * 2 + 0];
                float v1 = acc[mi][nj][half * 2 + 1];
                *(float2*)(Out + (size_t)bh * Tt * Dd + (size_t)t * Dd + dj * 128 + n0)
                    = make_float2(v0, v1);
            }
        }
    }
}

// ---------------------------------------------------------------------------
extern "C" void kernel_launch(void* const* d_in, const int* in_sizes, int n_in,
                              void* d_out, int out_size) {
    const float* Q      = (const float*)d_in[0];
    const float* V      = (const float*)d_in[1];
    const float* traces = (const float*)d_in[2];
    const float* scale  = (const float*)d_in[3];
    float* out = (float*)d_out;

    const size_t out_elems    = (size_t)BHh * Tt * Dd;
    const size_t scores_elems = (size_t)BHh * Tt * Tt;
    float* scores_dst;
    if ((size_t)out_size >= out_elems + scores_elems) {
        scores_dst = out + out_elems;
    } else {
        void* p = nullptr;
        cudaGetSymbolAddress(&p, g_S);
        scores_dst = (float*)p;
    }

    cudaFuncSetAttribute(scores_mma, cudaFuncAttributeMaxDynamicSharedMemorySize,
                         SCORES_SMEM);
    cudaFuncSetAttribute(out_mma, cudaFuncAttributeMaxDynamicSharedMemorySize,
                         OUT_SMEM);

    const int npairs = BHh * Tt * (Nn / 2);
    rope_kernel<<<(npairs + 255) / 256, 256>>>(Q);
    gate_kernel<<<(BHh * Tt * 32) / 256, 256>>>(traces);
    scores_mma<<<BHh * 64, 256, SCORES_SMEM>>>(scale, scores_dst);
    out_mma<<<BHh * 8 * 2, 256, OUT_SMEM>>>(V, scores_dst, out);
}

// round 10
// speedup vs baseline: 1.5632x; 1.1030x over previous
#include <cuda_runtime.h>
#include <cuda_fp16.h>
#include <cstdint>
#include <cstddef>

#define Bb   2
#define NH   4
#define Tt   1024
#define Nn   8192
#define Dd   256
#define BHh  (Bb*NH)

// Scratch (device globals; no allocations allowed)
__device__ __half g_QRh[(size_t)BHh * Tt * Nn];   // 128 MB RoPE'd Q, fp16
__device__ __half g_Sh[(size_t)BHh * Tt * Tt];    // 16 MB scores, fp16 (for out gemm)
__device__ __half g_Vh[(size_t)Bb * Dd * Tt];     // 1 MB V transposed [b][d][s], fp16
__device__ float  g_gate[BHh * Tt];
__device__ float  g_S[(size_t)BHh * Tt * Tt];     // 32 MB fallback scores buffer

__device__ __forceinline__ void cpasync16(uint32_t s, const void* g) {
    asm volatile("cp.async.cg.shared.global [%0], [%1], 16;" :: "r"(s), "l"(g));
}
__device__ __forceinline__ uint32_t smem_u32(const void* p) {
    uint32_t a;
    asm("{ .reg .u64 t; cvta.to.shared.u64 t, %1; cvt.u32.u64 %0, t; }"
        : "=r"(a) : "l"(p));
    return a;
}
__device__ __forceinline__ uint32_t lds32(uint32_t p) {
    uint32_t v;
    asm("ld.shared.b32 %0, [%1];" : "=r"(v) : "r"(p));
    return v;
}

// fp16 mma: m16n8k16, row.col, f32 accumulate
__device__ __forceinline__ void mma16(float c[4], const uint32_t a[4], const uint32_t b[2]) {
    asm volatile(
        "mma.sync.aligned.m16n8k16.row.col.f32.f16.f16.f32 "
        "{%0,%1,%2,%3}, {%4,%5,%6,%7}, {%8,%9}, {%0,%1,%2,%3};\n"
        : "+f"(c[0]), "+f"(c[1]), "+f"(c[2]), "+f"(c[3])
        : "r"(a[0]), "r"(a[1]), "r"(a[2]), "r"(a[3]), "r"(b[0]), "r"(b[1]));
}

// ---------------------------------------------------------------------------
// RoPE -> fp16: QRh[bh,t,n]
// ---------------------------------------------------------------------------
__global__ void rope_kernel(const float* __restrict__ Q) {
    size_t i = (size_t)blockIdx.x * blockDim.x + threadIdx.x;  // pair index
    const size_t npairs = (size_t)BHh * Tt * (Nn / 2);
    if (i >= npairs) return;
    int n2 = (int)(i & (Nn / 2 - 1));
    int t = (int)((i >> 12) & (Tt - 1));
    float nf = (float)(2 * n2);
    float freq = exp2f(-16.0f * nf / (float)Nn) * 0.15915494309189535f;
    float ph = (float)t * freq;
    ph -= floorf(ph);
    float sv, cv;
    __sincosf(ph * 6.283185307179586f, &sv, &cv);
    float2 q = ((const float2*)Q)[i];
    float e = q.x * cv - q.y * sv;
    float o = q.y * cv + q.x * sv;
    ((__half2*)g_QRh)[i] = __floats2half2_rn(e, o);
}

// ---------------------------------------------------------------------------
// gate[bh,t] = 0.5 + 0.5*sigmoid(mean_d traces[bh,t,d])
// ---------------------------------------------------------------------------
__global__ void gate_kernel(const float* __restrict__ traces) {
    int warp = (blockIdx.x * blockDim.x + threadIdx.x) >> 5;
    int lane = threadIdx.x & 31;
    if (warp >= BHh * Tt) return;
    const float4* p = (const float4*)(traces + (size_t)warp * Dd);
    float sum = 0.f;
    #pragma unroll
    for (int j = lane; j < Dd / 4; j += 32) {
        float4 v = p[j];
        sum += v.x + v.y + v.z + v.w;
    }
    #pragma unroll
    for (int o = 16; o; o >>= 1) sum += __shfl_xor_sync(0xffffffffu, sum, o);
    if (lane == 0) {
        float m = sum * (1.0f / Dd);
        float g = 1.0f / (1.0f + __expf(-m));
        g_gate[warp] = 0.5f + 0.5f * g;
    }
}

// ---------------------------------------------------------------------------
// V convert + transpose: g_Vh[b][d][s] = fp16(V[b][s][d])
// ---------------------------------------------------------------------------
__global__ void vconv_kernel(const float* __restrict__ V) {
    int i = blockIdx.x * blockDim.x + threadIdx.x;   // Bb*Dd*Tt = 524288
    if (i >= Bb * Dd * Tt) return;
    int s = i & (Tt - 1);
    int d = (i >> 10) & (Dd - 1);
    int b = i >> 18;
    g_Vh[i] = __float2half(V[((size_t)b * Tt + s) * Dd + d]);
}

// ---------------------------------------------------------------------------
// scores[bh,t,s]: 128x128 tile, 256 threads (8 warps @ 32x64), fp16 k16 MMA,
// cp.async 4-stage ring (K=64-half chunks = 128B rows), 1 bar/chunk.
// grid: bh*64 + ti*8 + si ; si>ti tiles zero-filled (f32 only).
// ---------------------------------------------------------------------------
#define KC      64
#define NCHUNK  (Nn / KC)                // 128
#define STAGE_B (256 * 128)              // (128 A + 128 B rows) * 128B = 32KB
#define SCORES_SMEM (4 * STAGE_B)        // 131072

__global__ __launch_bounds__(256, 1) void scores_mma(const float* __restrict__ scale_p,
                                                     float* __restrict__ Sout) {
    const int idx = blockIdx.x;
    const int bh = idx >> 6;
    const int ti = (idx >> 3) & 7;
    const int si = idx & 7;
    float* S = Sout + (size_t)bh * Tt * Tt;
    const int tid = threadIdx.x;

    if (si > ti) {  // strictly-upper block-tile: zero fill f32 output only
        float4 z = make_float4(0.f, 0.f, 0.f, 0.f);
        #pragma unroll
        for (int p = 0; p < 16; ++p) {
            int e = tid + p * 256;
            int r = e >> 5, c = (e & 31) * 4;
            *(float4*)(S + (size_t)(ti * 128 + r) * Tt + si * 128 + c) = z;
        }
        return;
    }

    extern __shared__ char smem[];
    const uint32_t sbase = smem_u32(smem);

    const __half* Ag = g_QRh + (size_t)bh * Tt * Nn + (size_t)(ti * 128) * Nn;
    const __half* Bg = g_QRh + (size_t)bh * Tt * Nn + (size_t)(si * 128) * Nn;

    const int warp = tid >> 5, lane = tid & 31;
    const int wm = (warp >> 1) * 32, wn = (warp & 1) * 64;
    const int gq = lane >> 2, tg = lane & 3;

    const int col = tid & 7;          // 16B granule (8 halfs)
    const int r0  = tid >> 3;         // 0..31

    auto load_stage = [&](int stage, int chunk) {
        const int k0 = chunk * KC;
        const uint32_t base = sbase + stage * STAGE_B;
        const __half* gA = Ag + k0 + col * 8;
        #pragma unroll
        for (int i = 0; i < 4; i++) {
            int r = r0 + i * 32;
            cpasync16(base + r * 128 + ((col ^ (r & 7)) << 4),
                      gA + (size_t)r * Nn);
        }
        const uint32_t bb = base + 128 * 128;
        const __half* gB = Bg + k0 + col * 8;
        #pragma unroll
        for (int i = 0; i < 4; i++) {
            int r = r0 + i * 32;
            cpasync16(bb + r * 128 + ((col ^ (r & 7)) << 4),
                      gB + (size_t)r * Nn);
        }
        asm volatile("cp.async.commit_group;" ::: "memory");
    };

    #pragma unroll
    for (int s = 0; s < 3; s++) load_stage(s, s);

    float acc[2][8][4];
    #pragma unroll
    for (int mi = 0; mi < 2; mi++)
        #pragma unroll
        for (int nj = 0; nj < 8; nj++)
            #pragma unroll
            for (int k = 0; k < 4; k++) acc[mi][nj][k] = 0.f;

    for (int c = 0; c < NCHUNK; c++) {
        asm volatile("cp.async.wait_group 2;" ::: "memory");
        __syncthreads();
        if (c + 3 < NCHUNK) load_stage((c + 3) & 3, c + 3);
        else asm volatile("cp.async.commit_group;" ::: "memory");

        const uint32_t abase = sbase + (c & 3) * STAGE_B;
        const uint32_t bbase = abase + 128 * 128;

        #pragma unroll
        for (int ks = 0; ks < 4; ks++) {   // 4 x k16 per 64-half chunk
            const uint32_t cax = (uint32_t)((32 * ks + 4 * tg) ^ (gq << 4));
            uint32_t a[2][4], b[8][2];
            #pragma unroll
            for (int mi = 0; mi < 2; mi++) {
                uint32_t p = abase + (uint32_t)((wm + mi * 16 + gq) * 128) + cax;
                a[mi][0] = lds32(p);
                a[mi][1] = lds32(p + 1024);
                a[mi][2] = lds32(p ^ 16);
                a[mi][3] = lds32((p + 1024) ^ 16);
            }
            #pragma unroll
            for (int nj = 0; nj < 8; nj++) {
                uint32_t p = bbase + (uint32_t)((wn + nj * 8 + gq) * 128) + cax;
                b[nj][0] = lds32(p);
                b[nj][1] = lds32(p ^ 16);
            }
            #pragma unroll
            for (int mi = 0; mi < 2; mi++)
                #pragma unroll
                for (int nj = 0; nj < 8; nj++)
                    mma16(acc[mi][nj], a[mi], b[nj]);
        }
    }

    // epilogue: STDP * strict-lower mask * gate; write f32 S + fp16 copy
    const float scale = *scale_p;
    __half* Sh = g_Sh + (size_t)bh * Tt * Tt;
    #pragma unroll
    for (int mi = 0; mi < 2; mi++) {
        #pragma unroll
        for (int half = 0; half < 2; ++half) {
            int t = ti * 128 + wm + mi * 16 + gq + half * 8;
            float gt = g_gate[bh * Tt + t];
            #pragma unroll
            for (int nj = 0; nj < 8; nj++) {
                int s0 = si * 128 + wn + nj * 8 + tg * 2;
                float v0 = acc[mi][nj][half * 2 + 0];
                float v1 = acc[mi][nj][half * 2 + 1];
                float o0 = (t > s0)
                    ? v0 * (1.0f + 0.01f * __expf((float)(s0 - t) * 0.05f) * scale) * gt : 0.f;
                float o1 = (t > s0 + 1)
                    ? v1 * (1.0f + 0.01f * __expf((float)(s0 + 1 - t) * 0.05f) * scale) * gt : 0.f;
                *(float2*)(S + (size_t)t * Tt + s0) = make_float2(o0, o1);
                *(__half2*)(Sh + (size_t)t * Tt + s0) = __floats2half2_rn(o0, o1);
            }
        }
    }
}

// ---------------------------------------------------------------------------
// out[bh,t,d] = sum_s Sh[bh,t,s] * Vh[b,d,s], fp16 k16 MMA, pipelined.
// grid: bh*16 + ti*2 + dj. CTA: 128 t-rows x 128 d-cols, K=(ti+1)*128 s.
// A stage: 128 t-rows x 128B (64 s-halfs). B stage: 128 d-rows x 128B.
// ---------------------------------------------------------------------------
#define OUT_SMEM (4 * STAGE_B)           // 131072

__global__ __launch_bounds__(256, 1) void out_mma(const float* __restrict__ Vunused,
                                                  float* __restrict__ Out) {
    const int idx = blockIdx.x;   // 8 bh * 8 ti * 2 dj
    const int bh = idx >> 4;
    const int ti = (idx >> 1) & 7;
    const int dj = idx & 1;
    const int b = bh >> 2;
    const __half* Ag = g_Sh + (size_t)bh * Tt * Tt + (size_t)(ti * 128) * Tt;
    const __half* Bg = g_Vh + (size_t)b * Dd * Tt + (size_t)(dj * 128) * Tt;
    const int tid = threadIdx.x;

    extern __shared__ char smem[];
    const uint32_t sbase = smem_u32(smem);

    const int warp = tid >> 5, lane = tid & 31;
    const int wm = (warp >> 1) * 32, wn = (warp & 1) * 64;
    const int gq = lane >> 2, tg = lane & 3;

    const int col = tid & 7, r0 = tid >> 3;

    auto load_stage = [&](int stage, int chunk) {
        const int k0 = chunk * KC;
        const uint32_t base = sbase + stage * STAGE_B;
        const __half* gA = Ag + k0 + col * 8;
        #pragma unroll
        for (int i = 0; i < 4; i++) {
            int r = r0 + i * 32;
            cpasync16(base + r * 128 + ((col ^ (r & 7)) << 4),
                      gA + (size_t)r * Tt);
        }
        const uint32_t bb = base + 128 * 128;
        const __half* gB = Bg + k0 + col * 8;
        #pragma unroll
        for (int i = 0; i < 4; i++) {
            int r = r0 + i * 32;
            cpasync16(bb + r * 128 + ((col ^ (r & 7)) << 4),
                      gB + (size_t)r * Tt);
        }
        asm volatile("cp.async.commit_group;" ::: "memory");
    };

    const int NKT = (ti + 1) * 2;   // chunks of 64 s-halfs
    #pragma unroll
    for (int s = 0; s < 3; s++) load_stage(s, s < NKT ? s : 0);

    float acc[2][8][4];
    #pragma unroll
    for (int mi = 0; mi < 2; mi++)
        #pragma unroll
        for (int nj = 0; nj < 8; nj++)
            #pragma unroll
            for (int k = 0; k < 4; k++) acc[mi][nj][k] = 0.f;

    for (int c = 0; c < NKT; c++) {
        asm volatile("cp.async.wait_group 2;" ::: "memory");
        __syncthreads();
        if (c + 3 < NKT) load_stage((c + 3) & 3, c + 3);
        else asm volatile("cp.async.commit_group;" ::: "memory");

        const uint32_t abase = sbase + (c & 3) * STAGE_B;
        const uint32_t bbase = abase + 128 * 128;

        #pragma unroll
        for (int ks = 0; ks < 4; ks++) {
            const uint32_t cax = (uint32_t)((32 * ks + 4 * tg) ^ (gq << 4));
            uint32_t a[2][4], bf[8][2];
            #pragma unroll
            for (int mi = 0; mi < 2; mi++) {
                uint32_t p = abase + (uint32_t)((wm + mi * 16 + gq) * 128) + cax;
                a[mi][0] = lds32(p);
                a[mi][1] = lds32(p + 1024);
                a[mi][2] = lds32(p ^ 16);
                a[mi][3] = lds32((p + 1024) ^ 16);
            }
            #pragma unroll
            for (int nj = 0; nj < 8; nj++) {
                uint32_t p = bbase + (uint32_t)((wn + nj * 8 + gq) * 128) + cax;
                bf[nj][0] = lds32(p);
                bf[nj][1] = lds32(p ^ 16);
            }
            #pragma unroll
            for (int mi = 0; mi < 2; mi++)
                #pragma unroll
                for (int nj = 0; nj < 8; nj++)
                    mma16(acc[mi][nj], a[mi], bf[nj]);
        }
    }

    #pragma unroll
    for (int mi = 0; mi < 2; mi++) {
        #pragma unroll
        for (int half = 0; half < 2; ++half) {
            int t = ti * 128 + wm + mi * 16 + gq + half * 8;
            #pragma unroll
            for (int nj = 0; nj < 8; nj++) {
                int n0 = wn + nj * 8 + tg * 2;
                float v0 = acc[mi][nj][half * 2 + 0];
                float v1 = acc[mi][nj][half * 2 + 1];
                *(float2*)(Out + (size_t)bh * Tt * Dd + (size_t)t * Dd + dj * 128 + n0)
                    = make_float2(v0, v1);
            }
        }
    }
}

// ---------------------------------------------------------------------------
extern "C" void kernel_launch(void* const* d_in, const int* in_sizes, int n_in,
                              void* d_out, int out_size) {
    const float* Q      = (const float*)d_in[0];
    const float* V      = (const float*)d_in[1];
    const float* traces = (const float*)d_in[2];
    const float* scale  = (const float*)d_in[3];
    float* out = (float*)d_out;

    const size_t out_elems    = (size_t)BHh * Tt * Dd;
    const size_t scores_elems = (size_t)BHh * Tt * Tt;
    float* scores_dst;
    if ((size_t)out_size >= out_elems + scores_elems) {
        scores_dst = out + out_elems;
    } else {
        void* p = nullptr;
        cudaGetSymbolAddress(&p, g_S);
        scores_dst = (float*)p;
    }

    cudaFuncSetAttribute(scores_mma, cudaFuncAttributeMaxDynamicSharedMemorySize,
                         SCORES_SMEM);
    cudaFuncSetAttribute(out_mma, cudaFuncAttributeMaxDynamicSharedMemorySize,
                         OUT_SMEM);

    const int npairs = BHh * Tt * (Nn / 2);
    rope_kernel<<<(npairs + 255) / 256, 256>>>(Q);
    gate_kernel<<<(BHh * Tt * 32) / 256, 256>>>(traces);
    vconv_kernel<<<(Bb * Dd * Tt + 255) / 256, 256>>>(V);
    scores_mma<<<BHh * 64, 256, SCORES_SMEM>>>(scale, scores_dst);
    out_mma<<<BHh * 8 * 2, 256, OUT_SMEM>>>(V, out);
}

// round 13
// speedup vs baseline: 2.3944x; 1.5317x over previous
#include <cuda_runtime.h>
#include <cuda_fp16.h>
#include <cstdint>
#include <cstddef>

#define Bb   2
#define NH   4
#define Tt   1024
#define Nn   8192
#define Dd   256
#define BHh  (Bb*NH)

// Scratch (device globals; no allocations allowed)
__device__ __half g_QRh[(size_t)BHh * Tt * Nn];   // 128 MB RoPE'd Q, fp16
__device__ __half g_Sh[(size_t)BHh * Tt * Tt];    // 16 MB scores, fp16 (for out gemm)
__device__ __half g_Vh[(size_t)Bb * Dd * Tt];     // 1 MB V transposed [b][d][s], fp16
__device__ float  g_gate[BHh * Tt];
__device__ float  g_S[(size_t)BHh * Tt * Tt];     // 32 MB fallback scores buffer

__device__ __forceinline__ void cpasync16(uint32_t s, const void* g) {
    asm volatile("cp.async.cg.shared.global [%0], [%1], 16;" :: "r"(s), "l"(g));
}
__device__ __forceinline__ uint32_t smem_u32(const void* p) {
    uint32_t a;
    asm("{ .reg .u64 t; cvta.to.shared.u64 t, %1; cvt.u32.u64 %0, t; }"
        : "=r"(a) : "l"(p));
    return a;
}

#define LDSM4(r, addr) \
    asm volatile("ldmatrix.sync.aligned.m8n8.x4.shared.b16 {%0,%1,%2,%3}, [%4];" \
        : "=r"((r)[0]), "=r"((r)[1]), "=r"((r)[2]), "=r"((r)[3]) : "r"(addr))

// fp16 mma: m16n8k16, row.col, f32 accumulate
__device__ __forceinline__ void mma16(float c[4], const uint32_t a[4], const uint32_t b0,
                                      const uint32_t b1) {
    asm volatile(
        "mma.sync.aligned.m16n8k16.row.col.f32.f16.f16.f32 "
        "{%0,%1,%2,%3}, {%4,%5,%6,%7}, {%8,%9}, {%0,%1,%2,%3};\n"
        : "+f"(c[0]), "+f"(c[1]), "+f"(c[2]), "+f"(c[3])
        : "r"(a[0]), "r"(a[1]), "r"(a[2]), "r"(a[3]), "r"(b0), "r"(b1));
}

// ---------------------------------------------------------------------------
// RoPE -> fp16: QRh[bh,t,n]
// ---------------------------------------------------------------------------
__global__ void rope_kernel(const float* __restrict__ Q) {
    size_t i = (size_t)blockIdx.x * blockDim.x + threadIdx.x;  // pair index
    const size_t npairs = (size_t)BHh * Tt * (Nn / 2);
    if (i >= npairs) return;
    int n2 = (int)(i & (Nn / 2 - 1));
    int t = (int)((i >> 12) & (Tt - 1));
    float nf = (float)(2 * n2);
    float freq = exp2f(-16.0f * nf / (float)Nn) * 0.15915494309189535f;
    float ph = (float)t * freq;
    ph -= floorf(ph);
    float sv, cv;
    __sincosf(ph * 6.283185307179586f, &sv, &cv);
    float2 q = ((const float2*)Q)[i];
    float e = q.x * cv - q.y * sv;
    float o = q.y * cv + q.x * sv;
    ((__half2*)g_QRh)[i] = __floats2half2_rn(e, o);
}

// ---------------------------------------------------------------------------
// gate[bh,t] = 0.5 + 0.5*sigmoid(mean_d traces[bh,t,d])
// ---------------------------------------------------------------------------
__global__ void gate_kernel(const float* __restrict__ traces) {
    int warp = (blockIdx.x * blockDim.x + threadIdx.x) >> 5;
    int lane = threadIdx.x & 31;
    if (warp >= BHh * Tt) return;
    const float4* p = (const float4*)(traces + (size_t)warp * Dd);
    float sum = 0.f;
    #pragma unroll
    for (int j = lane; j < Dd / 4; j += 32) {
        float4 v = p[j];
        sum += v.x + v.y + v.z + v.w;
    }
    #pragma unroll
    for (int o = 16; o; o >>= 1) sum += __shfl_xor_sync(0xffffffffu, sum, o);
    if (lane == 0) {
        float m = sum * (1.0f / Dd);
        float g = 1.0f / (1.0f + __expf(-m));
        g_gate[warp] = 0.5f + 0.5f * g;
    }
}

// ---------------------------------------------------------------------------
// V convert + transpose: g_Vh[b][d][s] = fp16(V[b][s][d])
// ---------------------------------------------------------------------------
__global__ void vconv_kernel(const float* __restrict__ V) {
    int i = blockIdx.x * blockDim.x + threadIdx.x;   // Bb*Dd*Tt = 524288
    if (i >= Bb * Dd * Tt) return;
    int s = i & (Tt - 1);
    int d = (i >> 10) & (Dd - 1);
    int b = i >> 18;
    g_Vh[i] = __float2half(V[((size_t)b * Tt + s) * Dd + d]);
}

// ---------------------------------------------------------------------------
// scores[bh,t,s]: 128x128 tile, 256 threads (8 warps @ 32x64), fp16 k16 MMA,
// ldmatrix fragment feed, cp.async 4-stage ring (K=64-half chunks), 1 bar/chunk.
// grid: bh*64 + ti*8 + si ; si>ti tiles zero-filled (f32 only).
// ---------------------------------------------------------------------------
#define KC      64
#define NCHUNK  (Nn / KC)                // 128
#define STAGE_B (256 * 128)              // (128 A + 128 B rows) * 128B = 32KB
#define SCORES_SMEM (4 * STAGE_B)        // 131072

__global__ __launch_bounds__(256, 1) void scores_mma(const float* __restrict__ scale_p,
                                                     float* __restrict__ Sout) {
    const int idx = blockIdx.x;
    const int bh = idx >> 6;
    const int ti = (idx >> 3) & 7;
    const int si = idx & 7;
    float* S = Sout + (size_t)bh * Tt * Tt;
    const int tid = threadIdx.x;

    if (si > ti) {  // strictly-upper block-tile: zero fill f32 output only
        float4 z = make_float4(0.f, 0.f, 0.f, 0.f);
        #pragma unroll
        for (int p = 0; p < 16; ++p) {
            int e = tid + p * 256;
            int r = e >> 5, c = (e & 31) * 4;
            *(float4*)(S + (size_t)(ti * 128 + r) * Tt + si * 128 + c) = z;
        }
        return;
    }

    extern __shared__ char smem[];
    const uint32_t sbase = smem_u32(smem);

    const __half* Ag = g_QRh + (size_t)bh * Tt * Nn + (size_t)(ti * 128) * Nn;
    const __half* Bg = g_QRh + (size_t)bh * Tt * Nn + (size_t)(si * 128) * Nn;

    const int warp = tid >> 5, lane = tid & 31;
    const int wm = (warp >> 1) * 32, wn = (warp & 1) * 64;
    const int gq = lane >> 2, tg = lane & 3;

    // per-lane ldmatrix row offsets (within a stage), swizzled, ks=0
    const int mat = lane >> 3, rin = lane & 7;
    uint32_t aoff[2], boff[4];
    #pragma unroll
    for (int mi = 0; mi < 2; mi++) {
        int row = wm + mi * 16 + (mat & 1) * 8 + rin;
        int gb = mat >> 1;
        aoff[mi] = (uint32_t)(row * 128 + ((gb ^ (row & 7)) << 4));
    }
    #pragma unroll
    for (int p = 0; p < 4; p++) {
        int nj = p * 2 + (mat >> 1);
        int gb = mat & 1;
        int row = wn + nj * 8 + rin;
        boff[p] = (uint32_t)(128 * 128 + row * 128 + ((gb ^ (row & 7)) << 4));
    }

    const int col = tid & 7;          // 16B granule (8 halfs)
    const int r0  = tid >> 3;         // 0..31

    auto load_stage = [&](int stage, int chunk) {
        const int k0 = chunk * KC;
        const uint32_t base = sbase + stage * STAGE_B;
        const __half* gA = Ag + k0 + col * 8;
        #pragma unroll
        for (int i = 0; i < 4; i++) {
            int r = r0 + i * 32;
            cpasync16(base + r * 128 + ((col ^ (r & 7)) << 4),
                      gA + (size_t)r * Nn);
        }
        const uint32_t bb = base + 128 * 128;
        const __half* gB = Bg + k0 + col * 8;
        #pragma unroll
        for (int i = 0; i < 4; i++) {
            int r = r0 + i * 32;
            cpasync16(bb + r * 128 + ((col ^ (r & 7)) << 4),
                      gB + (size_t)r * Nn);
        }
        asm volatile("cp.async.commit_group;" ::: "memory");
    };

    #pragma unroll
    for (int s = 0; s < 3; s++) load_stage(s, s);

    float acc[2][8][4];
    #pragma unroll
    for (int mi = 0; mi < 2; mi++)
        #pragma unroll
        for (int nj = 0; nj < 8; nj++)
            #pragma unroll
            for (int k = 0; k < 4; k++) acc[mi][nj][k] = 0.f;

    for (int c = 0; c < NCHUNK; c++) {
        asm volatile("cp.async.wait_group 2;" ::: "memory");
        __syncthreads();
        if (c + 3 < NCHUNK) load_stage((c + 3) & 3, c + 3);
        else asm volatile("cp.async.commit_group;" ::: "memory");

        const uint32_t abase = sbase + (c & 3) * STAGE_B;

        #pragma unroll
        for (int ks = 0; ks < 4; ks++) {   // 4 x k16 per 64-half chunk
            const uint32_t kx = (uint32_t)(ks << 5);
            uint32_t a[2][4], bq[4][4];
            #pragma unroll
            for (int mi = 0; mi < 2; mi++)
                LDSM4(a[mi], abase + (aoff[mi] ^ kx));
            #pragma unroll
            for (int p = 0; p < 4; p++)
                LDSM4(bq[p], abase + (boff[p] ^ kx));
            #pragma unroll
            for (int mi = 0; mi < 2; mi++)
                #pragma unroll
                for (int nj = 0; nj < 8; nj++)
                    mma16(acc[mi][nj], a[mi],
                          bq[nj >> 1][(nj & 1) * 2], bq[nj >> 1][(nj & 1) * 2 + 1]);
        }
    }

    // epilogue: STDP * strict-lower mask * gate; write f32 S + fp16 copy
    const float scale = *scale_p;
    __half* Sh = g_Sh + (size_t)bh * Tt * Tt;
    #pragma unroll
    for (int mi = 0; mi < 2; mi++) {
        #pragma unroll
        for (int half = 0; half < 2; ++half) {
            int t = ti * 128 + wm + mi * 16 + gq + half * 8;
            float gt = g_gate[bh * Tt + t];
            #pragma unroll
            for (int nj = 0; nj < 8; nj++) {
                int s0 = si * 128 + wn + nj * 8 + tg * 2;
                float v0 = acc[mi][nj][half * 2 + 0];
                float v1 = acc[mi][nj][half * 2 + 1];
                float o0 = (t > s0)
                    ? v0 * (1.0f + 0.01f * __expf((float)(s0 - t) * 0.05f) * scale) * gt : 0.f;
                float o1 = (t > s0 + 1)
                    ? v1 * (1.0f + 0.01f * __expf((float)(s0 + 1 - t) * 0.05f) * scale) * gt : 0.f;
                *(float2*)(S + (size_t)t * Tt + s0) = make_float2(o0, o1);
                *(__half2*)(Sh + (size_t)t * Tt + s0) = __floats2half2_rn(o0, o1);
            }
        }
    }
}

// ---------------------------------------------------------------------------
// out[bh,t,d] = sum_s Sh[bh,t,s] * Vh[b,d,s], fp16 k16 MMA + ldmatrix, pipelined.
// grid: bh*16 + ti*2 + dj. CTA: 128 t-rows x 128 d-cols, K=(ti+1)*128 s.
// ---------------------------------------------------------------------------
#define OUT_SMEM (4 * STAGE_B)           // 131072

__global__ __launch_bounds__(256, 1) void out_mma(float* __restrict__ Out) {
    const int idx = blockIdx.x;   // 8 bh * 8 ti * 2 dj
    const int bh = idx >> 4;
    const int ti = (idx >> 1) & 7;
    const int dj = idx & 1;
    const int b = bh >> 2;
    const __half* Ag = g_Sh + (size_t)bh * Tt * Tt + (size_t)(ti * 128) * Tt;
    const __half* Bg = g_Vh + (size_t)b * Dd * Tt + (size_t)(dj * 128) * Tt;
    const int tid = threadIdx.x;

    extern __shared__ char smem[];
    const uint32_t sbase = smem_u32(smem);

    const int warp = tid >> 5, lane = tid & 31;
    const int wm = (warp >> 1) * 32, wn = (warp & 1) * 64;
    const int gq = lane >> 2, tg = lane & 3;

    const int mat = lane >> 3, rin = lane & 7;
    uint32_t aoff[2], boff[4];
    #pragma unroll
    for (int mi = 0; mi < 2; mi++) {
        int row = wm + mi * 16 + (mat & 1) * 8 + rin;
        int gb = mat >> 1;
        aoff[mi] = (uint32_t)(row * 128 + ((gb ^ (row & 7)) << 4));
    }
    #pragma unroll
    for (int p = 0; p < 4; p++) {
        int nj = p * 2 + (mat >> 1);
        int gb = mat & 1;
        int row = wn + nj * 8 + rin;
        boff[p] = (uint32_t)(128 * 128 + row * 128 + ((gb ^ (row & 7)) << 4));
    }

    const int col = tid & 7, r0 = tid >> 3;

    auto load_stage = [&](int stage, int chunk) {
        const int k0 = chunk * KC;
        const uint32_t base = sbase + stage * STAGE_B;
        const __half* gA = Ag + k0 + col * 8;
        #pragma unroll
        for (int i = 0; i < 4; i++) {
            int r = r0 + i * 32;
            cpasync16(base + r * 128 + ((col ^ (r & 7)) << 4),
                      gA + (size_t)r * Tt);
        }
        const uint32_t bb = base + 128 * 128;
        const __half* gB = Bg + k0 + col * 8;
        #pragma unroll
        for (int i = 0; i < 4; i++) {
            int r = r0 + i * 32;
            cpasync16(bb + r * 128 + ((col ^ (r & 7)) << 4),
                      gB + (size_t)r * Tt);
        }
        asm volatile("cp.async.commit_group;" ::: "memory");
    };

    const int NKT = (ti + 1) * 2;   // chunks of 64 s-halfs
    #pragma unroll
    for (int s = 0; s < 3; s++) load_stage(s, s < NKT ? s : 0);

    float acc[2][8][4];
    #pragma unroll
    for (int mi = 0; mi < 2; mi++)
        #pragma unroll
        for (int nj = 0; nj < 8; nj++)
            #pragma unroll
            for (int k = 0; k < 4; k++) acc[mi][nj][k] = 0.f;

    for (int c = 0; c < NKT; c++) {
        asm volatile("cp.async.wait_group 2;" ::: "memory");
        __syncthreads();
        if (c + 3 < NKT) load_stage((c + 3) & 3, c + 3);
        else asm volatile("cp.async.commit_group;" ::: "memory");

        const uint32_t abase = sbase + (c & 3) * STAGE_B;

        #pragma unroll
        for (int ks = 0; ks < 4; ks++) {
            const uint32_t kx = (uint32_t)(ks << 5);
            uint32_t a[2][4], bq[4][4];
            #pragma unroll
            for (int mi = 0; mi < 2; mi++)
                LDSM4(a[mi], abase + (aoff[mi] ^ kx));
            #pragma unroll
            for (int p = 0; p < 4; p++)
                LDSM4(bq[p], abase + (boff[p] ^ kx));
            #pragma unroll
            for (int mi = 0; mi < 2; mi++)
                #pragma unroll
                for (int nj = 0; nj < 8; nj++)
                    mma16(acc[mi][nj], a[mi],
                          bq[nj >> 1][(nj & 1) * 2], bq[nj >> 1][(nj & 1) * 2 + 1]);
        }
    }

    #pragma unroll
    for (int mi = 0; mi < 2; mi++) {
        #pragma unroll
        for (int half = 0; half < 2; ++half) {
            int t = ti * 128 + wm + mi * 16 + gq + half * 8;
            #pragma unroll
            for (int nj = 0; nj < 8; nj++) {
                int n0 = wn + nj * 8 + tg * 2;
                float v0 = acc[mi][nj][half * 2 + 0];
                float v1 = acc[mi][nj][half * 2 + 1];
                *(float2*)(Out + (size_t)bh * Tt * Dd + (size_t)t * Dd + dj * 128 + n0)
                    = make_float2(v0, v1);
            }
        }
    }
}

// ---------------------------------------------------------------------------
extern "C" void kernel_launch(void* const* d_in, const int* in_sizes, int n_in,
                              void* d_out, int out_size) {
    const float* Q      = (const float*)d_in[0];
    const float* V      = (const float*)d_in[1];
    const float* traces = (const float*)d_in[2];
    const float* scale  = (const float*)d_in[3];
    float* out = (float*)d_out;

    const size_t out_elems    = (size_t)BHh * Tt * Dd;
    const size_t scores_elems = (size_t)BHh * Tt * Tt;
    float* scores_dst;
    if ((size_t)out_size >= out_elems + scores_elems) {
        scores_dst = out + out_elems;
    } else {
        void* p = nullptr;
        cudaGetSymbolAddress(&p, g_S);
        scores_dst = (float*)p;
    }

    cudaFuncSetAttribute(scores_mma, cudaFuncAttributeMaxDynamicSharedMemorySize,
                         SCORES_SMEM);
    cudaFuncSetAttribute(out_mma, cudaFuncAttributeMaxDynamicSharedMemorySize,
                         OUT_SMEM);

    const int npairs = BHh * Tt * (Nn / 2);
    rope_kernel<<<(npairs + 255) / 256, 256>>>(Q);
    gate_kernel<<<(BHh * Tt * 32) / 256, 256>>>(traces);
    vconv_kernel<<<(Bb * Dd * Tt + 255) / 256, 256>>>(V);
    scores_mma<<<BHh * 64, 256, SCORES_SMEM>>>(scale, scores_dst);
    out_mma<<<BHh * 8 * 2, 256, OUT_SMEM>>>(out);
}